// round 7
// baseline (speedup 1.0000x reference)
#include <cuda_runtime.h>
#include <math.h>

// MT 1D forward + loss, single fused kernel — diagonalized recursion,
// 4-WAY LAYER SPLIT per frequency (1 vector + 3 matrix warps).
//   Basis S = y+1, D = y-1 (y = Z/Zj): per layer
//     T = E*D ; S' = p*S - m*T ; D' = m*S - p*T,  p=(w+1)/2, m=(w-1)/2,
//     E = exp(-arg)(cos arg - i sin arg), w = sqrt(rho_j/rho_{j-1}).
//   role 0 (warps 0-3):  v <- A_j v for j = nL-1 .. 3*nm   (66 light steps)
//   role r=1..3:         M_r = A_{(r-1)nm} ... A_{r*nm-1}  (63 heavy steps,
//                        two identity columns, same step per column)
//   Combine: v_final = M1*(M2*(M3*v))  (one thread, 48 FMA).
//   4 warps/SMSP (block 512) so each warp's MUFU/FMA chain stalls are
//   filled by the other three.
// Exact pow2 renorm every 8 steps per warp; all scales cancel in the ratio.
// Loss reduction fused via fence + atomic ticket (reset for graph replay).

#define MU_F 1.2566370614359173e-6f
#define TWO_PI_F 6.283185307179586f
#define SQRT2_F 1.4142135623730951f
#define RAD2DEG_F 57.29577951308232f
#define NLOG2E_F (-1.4426950408889634f)

static __device__ float2 g_part[1024];
static __device__ unsigned g_ticket;   // zero-init; last block resets to 0

__device__ __forceinline__ void mk_e(float s, float4 L, float& ec, float& es)
{
    float arg = s * L.x;
    float e; asm("ex2.approx.ftz.f32 %0, %1;" : "=f"(e) : "f"(s * L.y));
    float sn, cs; __sincosf(arg, &sn, &cs);
    ec = e * cs; es = e * sn;          // E = ec - i*es
}

__device__ __forceinline__ void step_col(float p, float m, float ec, float es,
    float& Sre, float& Sim, float& Dre, float& Dim)
{
    float Tre = ec * Dre + es * Dim;
    float Tim = ec * Dim - es * Dre;
    float nSre = p * Sre - m * Tre;
    float nSim = p * Sim - m * Tim;
    float nDre = m * Sre - p * Tre;
    float nDim = m * Sim - p * Tim;
    Sre = nSre; Sim = nSim; Dre = nDre; Dim = nDim;
}

__device__ __forceinline__ float pow2_scale(float m0)
{
    float m = fmaxf(m0, 1e-30f);
    unsigned eb = __float_as_uint(m) & 0x7f800000u;
    return __uint_as_float(0x7f000000u - eb);
}

__global__ __launch_bounds__(512, 1) void mt_fused(
    const float* __restrict__ rho, const float* __restrict__ thick,
    const float* __restrict__ freq, const float* __restrict__ obs_r,
    const float* __restrict__ obs_p, float* __restrict__ out,
    int nz, int nf, float invnf)
{
    // Layer record: x = sqrt2*t/sqrt(rho), y = -log2e*x, z = p, w = m
    __shared__ float4 sL[512];
    __shared__ float4 sMat[3][128][4];   // [role-1][slot]{m11,m21,m12,m22}
    __shared__ float s_y0, s_rho0;
    __shared__ int s_last;

    const int tid = threadIdx.x;
    for (int j = tid; j < nz - 1; j += blockDim.x) {
        float r = rho[j];
        float T = SQRT2_F * thick[j] * rsqrtf(r);
        float w = (j > 0) ? sqrtf(r / rho[j - 1]) : 1.0f;
        sL[j] = make_float4(T, NLOG2E_F * T, 0.5f * (w + 1.f), 0.5f * (w - 1.f));
    }
    if (tid == 0) {
        s_y0 = sqrtf(rho[nz - 1] / rho[nz - 2]);
        s_rho0 = rho[0];
    }
    __syncthreads();

    const int slot = tid & 127;            // frequency slot within block
    const int role = tid >> 7;             // 0 = vector; 1..3 = matrix
    int i = blockIdx.x * 128 + slot;
    const bool valid = (i < nf);
    if (i >= nf) i = nf - 1;               // clamp: uniform execution

    const float omu = TWO_PI_F * freq[i] * MU_F;
    const float s = sqrtf(omu);

    const int nL = nz - 1;                 // layers applied j = nL-1 .. 0
    const int nm = nL >> 2;                // per-matrix segment length

    float Sre, Sim, Dre, Dim;              // vector state (role 0)

    if (role == 0) {
        // ---- vector: v <- A_j v, j = nL-1 .. 3*nm ----
        float y0 = s_y0;
        Sre = y0 + 1.f; Sim = 0.f; Dre = y0 - 1.f; Dim = 0.f;
        int j = nL - 1;
        int cnt = nL - 3 * nm;
        int rem = cnt & 7;
        #pragma unroll 1
        for (int k = 0; k < rem; ++k, --j) {
            float4 L = sL[j]; float ec, es; mk_e(s, L, ec, es);
            step_col(L.z, L.w, ec, es, Sre, Sim, Dre, Dim);
        }
        cnt -= rem;
        while (cnt > 0) {
            #pragma unroll
            for (int k = 0; k < 8; ++k) {
                float4 L = sL[j - k]; float ec, es; mk_e(s, L, ec, es);
                step_col(L.z, L.w, ec, es, Sre, Sim, Dre, Dim);
            }
            j -= 8; cnt -= 8;
            float sc = pow2_scale(fmaxf(fmaxf(fabsf(Sre), fabsf(Sim)),
                                        fmaxf(fabsf(Dre), fabsf(Dim))));
            Sre *= sc; Sim *= sc; Dre *= sc; Dim *= sc;
        }
    } else {
        // ---- matrix role r: M_r = prod of A_j, j = r*nm-1 .. (r-1)*nm ----
        float aSre = 1.f, aSim = 0.f, aDre = 0.f, aDim = 0.f;  // col1
        float bSre = 0.f, bSim = 0.f, bDre = 1.f, bDim = 0.f;  // col2
        int j = role * nm - 1;
        int cnt = nm;
        int rem = cnt & 7;
        #pragma unroll 1
        for (int k = 0; k < rem; ++k, --j) {
            float4 L = sL[j]; float ec, es; mk_e(s, L, ec, es);
            step_col(L.z, L.w, ec, es, aSre, aSim, aDre, aDim);
            step_col(L.z, L.w, ec, es, bSre, bSim, bDre, bDim);
        }
        cnt -= rem;
        while (cnt > 0) {
            #pragma unroll
            for (int k = 0; k < 8; ++k) {
                float4 L = sL[j - k]; float ec, es; mk_e(s, L, ec, es);
                step_col(L.z, L.w, ec, es, aSre, aSim, aDre, aDim);
                step_col(L.z, L.w, ec, es, bSre, bSim, bDre, bDim);
            }
            j -= 8; cnt -= 8;
            float m1 = fmaxf(fmaxf(fabsf(aSre), fabsf(aSim)),
                             fmaxf(fabsf(aDre), fabsf(aDim)));
            float m2 = fmaxf(fmaxf(fabsf(bSre), fabsf(bSim)),
                             fmaxf(fabsf(bDre), fabsf(bDim)));
            float sc = pow2_scale(fmaxf(m1, m2));
            aSre *= sc; aSim *= sc; aDre *= sc; aDim *= sc;
            bSre *= sc; bSim *= sc; bDre *= sc; bDim *= sc;
        }
        sMat[role - 1][slot][0] = make_float4(aSre, aSim, 0.f, 0.f);  // m11
        sMat[role - 1][slot][1] = make_float4(aDre, aDim, 0.f, 0.f);  // m21
        sMat[role - 1][slot][2] = make_float4(bSre, bSim, 0.f, 0.f);  // m12
        sMat[role - 1][slot][3] = make_float4(bDre, bDim, 0.f, 0.f);  // m22
    }

    __syncthreads();                       // matrices published

    float t1 = 0.f, t2 = 0.f;
    if (role == 0) {
        // v = M1 * (M2 * (M3 * v))
        #pragma unroll
        for (int r = 3; r >= 1; --r) {
            float4 m11 = sMat[r - 1][slot][0];
            float4 m21 = sMat[r - 1][slot][1];
            float4 m12 = sMat[r - 1][slot][2];
            float4 m22 = sMat[r - 1][slot][3];
            float nS_re = m11.x * Sre - m11.y * Sim + m12.x * Dre - m12.y * Dim;
            float nS_im = m11.x * Sim + m11.y * Sre + m12.x * Dim + m12.y * Dre;
            float nD_re = m21.x * Sre - m21.y * Sim + m22.x * Dre - m22.y * Dim;
            float nD_im = m21.x * Sim + m21.y * Sre + m22.x * Dim + m22.y * Dre;
            Sre = nS_re; Sim = nS_im; Dre = nD_re; Dim = nD_im;
        }

        // y = (S+D)/(S-D); Z = y*Z_L0, |Z_L0|^2 = omu*rho0, arg(Z_L0)=45deg
        float nre = Sre + Dre, nim = Sim + Dim;
        float dre = Sre - Dre, dim = Sim - Dim;
        float dd = dre * dre + dim * dim;
        float app_res = s_rho0 * (nre * nre + nim * nim) / dd;
        float yr = nre * dre + nim * dim;
        float yi = nim * dre - nre * dim;
        if (valid) {
            float dl = log10f(app_res) - log10f(obs_r[i]);
            t1 = dl * dl;
            float ph = atan2f(yi, yr) * RAD2DEG_F + 45.0f;
            float dp = ph - obs_p[i];
            t2 = dp * dp;
        }
    }

    // deterministic block reduction (16 warps)
    float x = t1, y = t2;
    #pragma unroll
    for (int o = 16; o > 0; o >>= 1) {
        x += __shfl_down_sync(0xffffffffu, x, o);
        y += __shfl_down_sync(0xffffffffu, y, o);
    }
    __shared__ float2 ws[16];
    int w = tid >> 5, l = tid & 31;
    if (l == 0) ws[w] = make_float2(x, y);
    __syncthreads();
    if (w == 0) {
        float2 vv = (l < 16) ? ws[l] : make_float2(0.f, 0.f);
        #pragma unroll
        for (int o = 8; o > 0; o >>= 1) {
            vv.x += __shfl_down_sync(0xffffffffu, vv.x, o);
            vv.y += __shfl_down_sync(0xffffffffu, vv.y, o);
        }
        if (l == 0) g_part[blockIdx.x] = vv;
    }

    // last-block final reduction (fence + ticket; reset keeps replays valid)
    __threadfence();
    if (tid == 0) {
        unsigned t = atomicAdd(&g_ticket, 1u);
        s_last = (t == gridDim.x - 1u);
    }
    __syncthreads();
    if (s_last) {
        int nb = gridDim.x;
        float fx = 0.f, fy = 0.f;
        for (int b = tid; b < nb; b += blockDim.x) {
            float2 p = g_part[b];
            fx += p.x; fy += p.y;
        }
        #pragma unroll
        for (int o = 16; o > 0; o >>= 1) {
            fx += __shfl_down_sync(0xffffffffu, fx, o);
            fy += __shfl_down_sync(0xffffffffu, fy, o);
        }
        __shared__ float2 ws2[16];
        if (l == 0) ws2[w] = make_float2(fx, fy);
        __syncthreads();
        if (tid == 0) {
            float gx = 0.f, gy = 0.f;
            int nw = (int)blockDim.x >> 5;
            for (int q = 0; q < nw; ++q) { gx += ws2[q].x; gy += ws2[q].y; }
            float lr = gx * invnf;
            float lp = gy * invnf;
            out[0] = lr + 10.f * lp;
            out[1] = lr;
            out[2] = lp;
            g_ticket = 0u;   // reset for next graph replay
        }
    }
}

extern "C" void kernel_launch(void* const* d_in, const int* in_sizes, int n_in,
                              void* d_out, int out_size)
{
    const float* rho    = (const float*)d_in[0];
    const float* thick  = (const float*)d_in[1];
    const float* freq   = (const float*)d_in[2];
    const float* obs_r  = (const float*)d_in[3];
    const float* obs_p  = (const float*)d_in[4];
    int nz = in_sizes[0];
    int nf = in_sizes[2];
    int blocks = (nf + 127) / 128;     // 128 freqs per block (512 threads)
    if (blocks > 1024) blocks = 1024;  // g_part capacity (nf=16384 -> 128)
    mt_fused<<<blocks, 512>>>(rho, thick, freq, obs_r, obs_p,
                              (float*)d_out, nz, nf, 1.f / (float)nf);
}

// round 8
// speedup vs baseline: 1.0108x; 1.0108x over previous
#include <cuda_runtime.h>
#include <math.h>

// MT 1D forward + loss, single fused kernel — diagonalized recursion with an
// EXPLICIT DEPTH-2 SOFTWARE PIPELINE (coefficients of step j-1 computed in
// program order before the state update of step j, so the LDS/MUFU latency of
// the next step hides under the current step's FMA tree).
//   Basis S = y+1, D = y-1 (y = Z/Zj): per layer
//     T = E*D ; S' = p*S - m*T ; D' = m*S - p*T,  p=(w+1)/2, m=(w-1)/2,
//     E = exp(-arg)(cos arg - i sin arg), arg = sqrt2*t*sqrt(omega*mu/rho),
//     w = sqrt(rho_j/rho_{j-1}).
// Per step: 16 FMA-pipe + 3 MUFU + 1 LDS.128. Loop-carried chain is only
// T -> D' (~3 FMA deep); everything else pipelines.
// Layer j is stored at sLs[j+1] (sLs[0] = dummy) so the next-step prefetch
// at j=0 stays in bounds without a branch.
// Exact pow2 renorm every 8 steps (cancels in the S/D ratio).
// Loss reduction fused via fence + atomic ticket (reset for graph replay).

#define MU_F 1.2566370614359173e-6f
#define TWO_PI_F 6.283185307179586f
#define SQRT2_F 1.4142135623730951f
#define RAD2DEG_F 57.29577951308232f
#define NLOG2E_F (-1.4426950408889634f)

static __device__ float2 g_part[1024];
static __device__ unsigned g_ticket;   // zero-init; last block resets to 0

// coefficient set for one layer
struct Cf { float ec, es, p, m; };

__device__ __forceinline__ Cf mk_cf(float s, float4 L)
{
    Cf c;
    float arg = s * L.x;
    float e; asm("ex2.approx.ftz.f32 %0, %1;" : "=f"(e) : "f"(s * L.y));
    float sn, cs; __sincosf(arg, &sn, &cs);
    c.ec = e * cs; c.es = e * sn;      // E = ec - i*es
    c.p = L.z; c.m = L.w;
    return c;
}

__device__ __forceinline__ void apply_cf(const Cf& c,
    float& Sre, float& Sim, float& Dre, float& Dim)
{
    float Tre = c.ec * Dre + c.es * Dim;
    float Tim = c.ec * Dim - c.es * Dre;
    float nSre = c.p * Sre - c.m * Tre;
    float nSim = c.p * Sim - c.m * Tim;
    float nDre = c.m * Sre - c.p * Tre;
    float nDim = c.m * Sim - c.p * Tim;
    Sre = nSre; Sim = nSim; Dre = nDre; Dim = nDim;
}

__device__ __forceinline__ float pow2_scale(float m0)
{
    float m = fmaxf(m0, 1e-30f);
    unsigned eb = __float_as_uint(m) & 0x7f800000u;
    return __uint_as_float(0x7f000000u - eb);
}

__global__ __launch_bounds__(128, 1) void mt_fused(
    const float* __restrict__ rho, const float* __restrict__ thick,
    const float* __restrict__ freq, const float* __restrict__ obs_r,
    const float* __restrict__ obs_p, float* __restrict__ out,
    int nz, int nf, float invnf)
{
    // Layer record at sLs[j+1]: x = sqrt2*t/sqrt(rho), y = -log2e*x, z=p, w=m
    __shared__ float4 sLs[513];
    __shared__ float s_y0, s_rho0;
    __shared__ int s_last;

    const int tid = threadIdx.x;
    for (int j = tid; j < nz - 1; j += blockDim.x) {
        float r = rho[j];
        float T = SQRT2_F * thick[j] * rsqrtf(r);
        float w = (j > 0) ? sqrtf(r / rho[j - 1]) : 1.0f;
        sLs[j + 1] = make_float4(T, NLOG2E_F * T,
                                 0.5f * (w + 1.f), 0.5f * (w - 1.f));
    }
    if (tid == 0) {
        sLs[0] = make_float4(0.f, 0.f, 1.f, 0.f);   // dummy prefetch target
        s_y0 = sqrtf(rho[nz - 1] / rho[nz - 2]);
        s_rho0 = rho[0];
    }
    __syncthreads();

    const int i = blockIdx.x * blockDim.x + tid;
    float t1 = 0.f, t2 = 0.f;
    if (i < nf) {
        const float omu = TWO_PI_F * freq[i] * MU_F;
        const float s = sqrtf(omu);
        const float y0 = s_y0;
        float Sre = y0 + 1.f, Sim = 0.f;
        float Dre = y0 - 1.f, Dim = 0.f;

        const int nL = nz - 1;         // steps j = nL-1 .. 0
        int j = nL - 1;
        int rem = nL & 7;              // peel so bulk is blocks of 8
        #pragma unroll 1
        for (int k = 0; k < rem; ++k, --j) {
            Cf c = mk_cf(s, sLs[j + 1]);
            apply_cf(c, Sre, Sim, Dre, Dim);
        }
        {
            float sc = pow2_scale(fmaxf(fmaxf(fabsf(Sre), fabsf(Sim)),
                                        fmaxf(fabsf(Dre), fabsf(Dim))));
            Sre *= sc; Sim *= sc; Dre *= sc; Dim *= sc;
        }

        // ---- pipelined bulk: coef for step j is ready before its apply ----
        Cf c0 = mk_cf(s, sLs[j + 1]);      // prime: coef for current j
        #pragma unroll 1
        while (j >= 7) {
            #pragma unroll
            for (int k = 0; k < 8; ++k) {
                // prefetch + coefficients for NEXT step (layer j-1 at sLs[j])
                Cf c1 = mk_cf(s, sLs[j - k]);
                // state update for CURRENT step (hides c1's LDS/MUFU latency)
                apply_cf(c0, Sre, Sim, Dre, Dim);
                c0 = c1;
            }
            j -= 8;
            float sc = pow2_scale(fmaxf(fmaxf(fabsf(Sre), fabsf(Sim)),
                                        fmaxf(fabsf(Dre), fabsf(Dim))));
            Sre *= sc; Sim *= sc; Dre *= sc; Dim *= sc;
        }
        // j == -1 here: all nL steps applied (last c0 consumed in final k=7;
        // the final prefetched c1 came from dummy sLs[0] and is discarded).

        // y = (S+D)/(S-D); Z = y*Z_L0, |Z_L0|^2 = omu*rho0, arg(Z_L0)=45deg
        float nre = Sre + Dre, nim = Sim + Dim;
        float dre = Sre - Dre, dim = Sim - Dim;
        float dd = dre * dre + dim * dim;
        float app_res = s_rho0 * (nre * nre + nim * nim) / dd;
        float yr = nre * dre + nim * dim;
        float yi = nim * dre - nre * dim;
        float dl = log10f(app_res) - log10f(obs_r[i]);
        t1 = dl * dl;
        float ph = atan2f(yi, yr) * RAD2DEG_F + 45.0f;
        float dp = ph - obs_p[i];
        t2 = dp * dp;
    }

    // deterministic block reduction
    float x = t1, y = t2;
    #pragma unroll
    for (int o = 16; o > 0; o >>= 1) {
        x += __shfl_down_sync(0xffffffffu, x, o);
        y += __shfl_down_sync(0xffffffffu, y, o);
    }
    __shared__ float2 ws[4];
    int w = tid >> 5, l = tid & 31;
    if (l == 0) ws[w] = make_float2(x, y);
    __syncthreads();
    if (w == 0) {
        float2 vv = (l < 4) ? ws[l] : make_float2(0.f, 0.f);
        #pragma unroll
        for (int o = 2; o > 0; o >>= 1) {
            vv.x += __shfl_down_sync(0xffffffffu, vv.x, o);
            vv.y += __shfl_down_sync(0xffffffffu, vv.y, o);
        }
        if (l == 0) g_part[blockIdx.x] = vv;
    }

    // last-block final reduction (fence + ticket; reset keeps replays valid)
    __threadfence();
    if (tid == 0) {
        unsigned t = atomicAdd(&g_ticket, 1u);
        s_last = (t == gridDim.x - 1u);
    }
    __syncthreads();
    if (s_last) {
        int nb = gridDim.x;
        float fx = 0.f, fy = 0.f;
        for (int b = tid; b < nb; b += blockDim.x) {
            float2 p = g_part[b];
            fx += p.x; fy += p.y;
        }
        #pragma unroll
        for (int o = 16; o > 0; o >>= 1) {
            fx += __shfl_down_sync(0xffffffffu, fx, o);
            fy += __shfl_down_sync(0xffffffffu, fy, o);
        }
        __shared__ float2 ws2[4];
        if (l == 0) ws2[w] = make_float2(fx, fy);
        __syncthreads();
        if (tid == 0) {
            float gx = 0.f, gy = 0.f;
            int nw = (int)blockDim.x >> 5;
            for (int q = 0; q < nw; ++q) { gx += ws2[q].x; gy += ws2[q].y; }
            float lr = gx * invnf;
            float lp = gy * invnf;
            out[0] = lr + 10.f * lp;
            out[1] = lr;
            out[2] = lp;
            g_ticket = 0u;   // reset for next graph replay
        }
    }
}

extern "C" void kernel_launch(void* const* d_in, const int* in_sizes, int n_in,
                              void* d_out, int out_size)
{
    const float* rho    = (const float*)d_in[0];
    const float* thick  = (const float*)d_in[1];
    const float* freq   = (const float*)d_in[2];
    const float* obs_r  = (const float*)d_in[3];
    const float* obs_p  = (const float*)d_in[4];
    int nz = in_sizes[0];
    int nf = in_sizes[2];
    int blocks = (nf + 127) / 128;
    if (blocks > 1024) blocks = 1024;  // g_part capacity (nf=16384 -> 128)
    mt_fused<<<blocks, 128>>>(rho, thick, freq, obs_r, obs_p,
                              (float*)d_out, nz, nf, 1.f / (float)nf);
}

// round 9
// speedup vs baseline: 1.0468x; 1.0356x over previous
#include <cuda_runtime.h>
#include <math.h>

// MT 1D forward + loss, single fused kernel — diagonalized + PROJECTIVE
// q-form recursion (12 FMA-pipe ops per step).
//   Basis S = y+1, D = y-1 (y = Z/Zj). Per layer the transfer matrix
//   [[p, -mE],[m, -pE]] = p * [[1, -qE],[q, -E]],  q = (w-1)/(w+1),
//   w = sqrt(rho_j/rho_{j-1}); the real scalar p cancels in (S+D)/(S-D),
//   so the step reduces to
//     T = E*D ; S' = S - q*T ; D' = q*S - T
//   with E = exp(-arg)(cos arg - i sin arg), arg = sqrt2*t*sqrt(omega*mu/rho).
// Per step: 12 FMA-pipe + 3 MUFU + 1 LDS.128.
// Exact pow2 renorm every 8 steps (cancels in the S/D ratio).
// Loss reduction fused via fence + atomic ticket (reset for graph replay).

#define MU_F 1.2566370614359173e-6f
#define TWO_PI_F 6.283185307179586f
#define SQRT2_F 1.4142135623730951f
#define RAD2DEG_F 57.29577951308232f
#define NLOG2E_F (-1.4426950408889634f)

static __device__ float2 g_part[1024];
static __device__ unsigned g_ticket;   // zero-init; last block resets to 0

struct Cf { float ec, es, q; };

__device__ __forceinline__ Cf mk_cf(float s, float4 L)
{
    // L.x = sqrt2*t/sqrt(rho), L.y = -log2e*L.x, L.z = q
    Cf c;
    float arg = s * L.x;
    float e; asm("ex2.approx.ftz.f32 %0, %1;" : "=f"(e) : "f"(s * L.y));
    float sn, cs; __sincosf(arg, &sn, &cs);
    c.ec = e * cs; c.es = e * sn;      // E = ec - i*es
    c.q = L.z;
    return c;
}

__device__ __forceinline__ void apply_cf(const Cf& c,
    float& Sre, float& Sim, float& Dre, float& Dim)
{
    float Tre = c.ec * Dre + c.es * Dim;   // T = E*D
    float Tim = c.ec * Dim - c.es * Dre;
    float nSre = Sre - c.q * Tre;          // S' = S - q*T
    float nSim = Sim - c.q * Tim;
    float nDre = c.q * Sre - Tre;          // D' = q*S - T
    float nDim = c.q * Sim - Tim;
    Sre = nSre; Sim = nSim; Dre = nDre; Dim = nDim;
}

__device__ __forceinline__ float pow2_scale(float m0)
{
    float m = fmaxf(m0, 1e-30f);
    unsigned eb = __float_as_uint(m) & 0x7f800000u;
    return __uint_as_float(0x7f000000u - eb);
}

__global__ __launch_bounds__(128, 1) void mt_fused(
    const float* __restrict__ rho, const float* __restrict__ thick,
    const float* __restrict__ freq, const float* __restrict__ obs_r,
    const float* __restrict__ obs_p, float* __restrict__ out,
    int nz, int nf, float invnf)
{
    // Layer j stored at sLs[j+1]; sLs[0] = dummy prefetch target.
    __shared__ float4 sLs[513];
    __shared__ float s_y0, s_rho0;
    __shared__ int s_last;

    const int tid = threadIdx.x;
    for (int j = tid; j < nz - 1; j += blockDim.x) {
        float r = rho[j];
        float T = SQRT2_F * thick[j] * rsqrtf(r);
        float w = (j > 0) ? sqrtf(r / rho[j - 1]) : 1.0f;
        float q = (w - 1.f) / (w + 1.f);
        sLs[j + 1] = make_float4(T, NLOG2E_F * T, q, 0.f);
    }
    if (tid == 0) {
        sLs[0] = make_float4(0.f, 0.f, 0.f, 0.f);
        s_y0 = sqrtf(rho[nz - 1] / rho[nz - 2]);
        s_rho0 = rho[0];
    }
    __syncthreads();

    const int i = blockIdx.x * blockDim.x + tid;
    float t1 = 0.f, t2 = 0.f;
    if (i < nf) {
        const float omu = TWO_PI_F * freq[i] * MU_F;
        const float s = sqrtf(omu);
        const float y0 = s_y0;
        float Sre = y0 + 1.f, Sim = 0.f;
        float Dre = y0 - 1.f, Dim = 0.f;

        const int nL = nz - 1;         // steps j = nL-1 .. 0
        int j = nL - 1;
        int rem = nL & 7;              // peel so bulk is blocks of 8
        #pragma unroll 1
        for (int k = 0; k < rem; ++k, --j) {
            Cf c = mk_cf(s, sLs[j + 1]);
            apply_cf(c, Sre, Sim, Dre, Dim);
        }
        {
            float sc = pow2_scale(fmaxf(fmaxf(fabsf(Sre), fabsf(Sim)),
                                        fmaxf(fabsf(Dre), fabsf(Dim))));
            Sre *= sc; Sim *= sc; Dre *= sc; Dim *= sc;
        }

        // depth-2 pipelined bulk (coef of next step in program order before
        // the current state update)
        Cf c0 = mk_cf(s, sLs[j + 1]);
        #pragma unroll 1
        while (j >= 7) {
            #pragma unroll
            for (int k = 0; k < 8; ++k) {
                Cf c1 = mk_cf(s, sLs[j - k]);      // next step's coef
                apply_cf(c0, Sre, Sim, Dre, Dim);  // current step
                c0 = c1;
            }
            j -= 8;
            float sc = pow2_scale(fmaxf(fmaxf(fabsf(Sre), fabsf(Sim)),
                                        fmaxf(fabsf(Dre), fabsf(Dim))));
            Sre *= sc; Sim *= sc; Dre *= sc; Dim *= sc;
        }
        // j == -1: all steps applied (final prefetch hit dummy sLs[0]).

        // y = (S+D)/(S-D); Z = y*Z_L0, |Z_L0|^2 = omu*rho0, arg(Z_L0)=45deg
        float nre = Sre + Dre, nim = Sim + Dim;
        float dre = Sre - Dre, dim = Sim - Dim;
        float dd = dre * dre + dim * dim;
        float app_res = s_rho0 * (nre * nre + nim * nim) / dd;
        float yr = nre * dre + nim * dim;
        float yi = nim * dre - nre * dim;
        float dl = log10f(app_res) - log10f(obs_r[i]);
        t1 = dl * dl;
        float ph = atan2f(yi, yr) * RAD2DEG_F + 45.0f;
        float dp = ph - obs_p[i];
        t2 = dp * dp;
    }

    // deterministic block reduction
    float x = t1, y = t2;
    #pragma unroll
    for (int o = 16; o > 0; o >>= 1) {
        x += __shfl_down_sync(0xffffffffu, x, o);
        y += __shfl_down_sync(0xffffffffu, y, o);
    }
    __shared__ float2 ws[4];
    int w = tid >> 5, l = tid & 31;
    if (l == 0) ws[w] = make_float2(x, y);
    __syncthreads();
    if (w == 0) {
        float2 vv = (l < 4) ? ws[l] : make_float2(0.f, 0.f);
        #pragma unroll
        for (int o = 2; o > 0; o >>= 1) {
            vv.x += __shfl_down_sync(0xffffffffu, vv.x, o);
            vv.y += __shfl_down_sync(0xffffffffu, vv.y, o);
        }
        if (l == 0) g_part[blockIdx.x] = vv;
    }

    // last-block final reduction (fence + ticket; reset keeps replays valid)
    __threadfence();
    if (tid == 0) {
        unsigned t = atomicAdd(&g_ticket, 1u);
        s_last = (t == gridDim.x - 1u);
    }
    __syncthreads();
    if (s_last) {
        int nb = gridDim.x;
        float fx = 0.f, fy = 0.f;
        for (int b = tid; b < nb; b += blockDim.x) {
            float2 p = g_part[b];
            fx += p.x; fy += p.y;
        }
        #pragma unroll
        for (int o = 16; o > 0; o >>= 1) {
            fx += __shfl_down_sync(0xffffffffu, fx, o);
            fy += __shfl_down_sync(0xffffffffu, fy, o);
        }
        __shared__ float2 ws2[4];
        if (l == 0) ws2[w] = make_float2(fx, fy);
        __syncthreads();
        if (tid == 0) {
            float gx = 0.f, gy = 0.f;
            int nw = (int)blockDim.x >> 5;
            for (int q = 0; q < nw; ++q) { gx += ws2[q].x; gy += ws2[q].y; }
            float lr = gx * invnf;
            float lp = gy * invnf;
            out[0] = lr + 10.f * lp;
            out[1] = lr;
            out[2] = lp;
            g_ticket = 0u;   // reset for next graph replay
        }
    }
}

extern "C" void kernel_launch(void* const* d_in, const int* in_sizes, int n_in,
                              void* d_out, int out_size)
{
    const float* rho    = (const float*)d_in[0];
    const float* thick  = (const float*)d_in[1];
    const float* freq   = (const float*)d_in[2];
    const float* obs_r  = (const float*)d_in[3];
    const float* obs_p  = (const float*)d_in[4];
    int nz = in_sizes[0];
    int nf = in_sizes[2];
    int blocks = (nf + 127) / 128;
    if (blocks > 1024) blocks = 1024;  // g_part capacity (nf=16384 -> 128)
    mt_fused<<<blocks, 128>>>(rho, thick, freq, obs_r, obs_p,
                              (float*)d_out, nz, nf, 1.f / (float)nf);
}